// round 1
// baseline (speedup 1.0000x reference)
#include <cuda_runtime.h>
#include <math.h>

#define BB 4
#define CC 192
#define C2 384
#define HWN 16384
#define HIMG 128
#define NHEADS 4
#define CHD 48
#define HIDC 510
#define HID2 1020
#define EPSLN 1e-5f

// ---------------- scratch (static device memory; no runtime alloc) ----------
__device__ float g_xn  [BB*CC*HWN];
__device__ float g_kv1n[BB*CC*HWN];
__device__ float g_kv2n[BB*CC*HWN];
__device__ float g_qpre [BB*C2*HWN];
__device__ float g_kv1pre[BB*C2*HWN];
__device__ float g_kv2pre[BB*C2*HWN];
__device__ float g_q   [BB*C2*HWN];
__device__ float g_kv1 [BB*C2*HWN];
__device__ float g_kv2 [BB*C2*HWN];
__device__ float g_ao  [BB*C2*HWN];
__device__ float g_x2  [BB*CC*HWN];
__device__ float g_h   [BB*HID2*HWN];
__device__ float g_hd  [BB*HID2*HWN];
__device__ float g_gg  [BB*HIDC*HWN];
__device__ float g_S   [32*CHD*CHD];
__device__ float g_nrm [32*2*CHD];

// ---------------- LayerNorm over channel dim, NCHW ----------------
__global__ void ln_kernel(const float* __restrict__ X, const float* __restrict__ w,
                          const float* __restrict__ bia, float* __restrict__ Y) {
    int b = blockIdx.y;
    int p = blockIdx.x * 256 + threadIdx.x;
    const float* xp = X + (size_t)b * CC * HWN + p;
    float mu = 0.f;
    #pragma unroll 4
    for (int c = 0; c < CC; c++) mu += xp[(size_t)c * HWN];
    mu *= (1.f / CC);
    float var = 0.f;
    #pragma unroll 4
    for (int c = 0; c < CC; c++) { float d = xp[(size_t)c * HWN] - mu; var += d * d; }
    var *= (1.f / CC);
    float inv = rsqrtf(var + EPSLN);
    float* yp = Y + (size_t)b * CC * HWN + p;
    #pragma unroll 4
    for (int c = 0; c < CC; c++)
        yp[(size_t)c * HWN] = (xp[(size_t)c * HWN] - mu) * inv * w[c] + bia[c];
}

// ---------------- 1x1 conv as SGEMM: Y[b][o][p] = sum_c W[o][c] X[b][c][p] ---
template<bool RESID>
__global__ void gemm1x1(const float* __restrict__ W, const float* __restrict__ X,
                        const float* __restrict__ R, float* __restrict__ Y,
                        int O, int Cin) {
    const int BM = 128, BN = 128, BK = 8;
    __shared__ float As[BK][BM];
    __shared__ float Bs[BK][BN + 4];
    int b  = blockIdx.z;
    int p0 = blockIdx.x * BN;
    int o0 = blockIdx.y * BM;
    int t  = threadIdx.x;
    int tm = (t >> 4) * 8;
    int tn = (t & 15) * 8;
    float acc[8][8];
    #pragma unroll
    for (int i = 0; i < 8; i++)
        #pragma unroll
        for (int j = 0; j < 8; j++) acc[i][j] = 0.f;

    const float* Xb = X + (size_t)b * Cin * HWN;
    for (int k0 = 0; k0 < Cin; k0 += BK) {
        #pragma unroll
        for (int i = t; i < BM * BK; i += 256) {
            int m = i >> 3, k = i & 7;
            int o = o0 + m, c = k0 + k;
            As[k][m] = (o < O && c < Cin) ? W[(size_t)o * Cin + c] : 0.f;
        }
        #pragma unroll
        for (int i = t; i < BK * BN; i += 256) {
            int k = i >> 7, n = i & 127;
            int c = k0 + k;
            Bs[k][n] = (c < Cin) ? Xb[(size_t)c * HWN + p0 + n] : 0.f;
        }
        __syncthreads();
        #pragma unroll
        for (int k = 0; k < BK; k++) {
            float ra[8], rb[8];
            #pragma unroll
            for (int i = 0; i < 8; i++) ra[i] = As[k][tm + i];
            #pragma unroll
            for (int j = 0; j < 8; j++) rb[j] = Bs[k][tn + j];
            #pragma unroll
            for (int i = 0; i < 8; i++)
                #pragma unroll
                for (int j = 0; j < 8; j++) acc[i][j] += ra[i] * rb[j];
        }
        __syncthreads();
    }
    float* Yb = Y + (size_t)b * O * HWN;
    const float* Rb = R + (size_t)b * O * HWN;
    #pragma unroll
    for (int i = 0; i < 8; i++) {
        int o = o0 + tm + i;
        if (o >= O) break;
        #pragma unroll
        for (int j = 0; j < 8; j++) {
            int p = p0 + tn + j;
            float v = acc[i][j];
            if (RESID) v += Rb[(size_t)o * HWN + p];
            Yb[(size_t)o * HWN + p] = v;
        }
    }
}

// ---------------- depthwise 3x3, 1 channel per group ----------------
__global__ void dwconv_dw(const float* __restrict__ X, const float* __restrict__ Wt,
                          float* __restrict__ Y, int Ctot) {
    int b = blockIdx.z, c = blockIdx.y;
    int p = blockIdx.x * 256 + threadIdx.x;
    int h = p >> 7, w = p & (HIMG - 1);
    const float* xp = X + ((size_t)b * Ctot + c) * HWN;
    const float* wp = Wt + (size_t)c * 9;
    float s = 0.f;
    #pragma unroll
    for (int dy = -1; dy <= 1; dy++) {
        int hh = h + dy;
        if (hh < 0 || hh >= HIMG) continue;
        #pragma unroll
        for (int dx = -1; dx <= 1; dx++) {
            int ww = w + dx;
            if (ww < 0 || ww >= HIMG) continue;
            s += wp[(dy + 1) * 3 + (dx + 1)] * xp[hh * HIMG + ww];
        }
    }
    Y[((size_t)b * Ctot + c) * HWN + p] = s;
}

// ---------------- grouped 3x3, groups=192, 2 in / 2 out per group -----------
__global__ void dwconv_g2(const float* __restrict__ X, const float* __restrict__ Wt,
                          float* __restrict__ Y) {
    int b = blockIdx.z, o = blockIdx.y;  // o in [0,384)
    int p = blockIdx.x * 256 + threadIdx.x;
    int h = p >> 7, w = p & (HIMG - 1);
    int i0 = (o >> 1) << 1;
    const float* x0 = X + ((size_t)b * C2 + i0) * HWN;
    const float* wp = Wt + (size_t)o * 18;
    float s = 0.f;
    #pragma unroll
    for (int ic = 0; ic < 2; ic++) {
        const float* xp = x0 + (size_t)ic * HWN;
        const float* wq = wp + ic * 9;
        #pragma unroll
        for (int dy = -1; dy <= 1; dy++) {
            int hh = h + dy;
            if (hh < 0 || hh >= HIMG) continue;
            #pragma unroll
            for (int dx = -1; dx <= 1; dx++) {
                int ww = w + dx;
                if (ww < 0 || ww >= HIMG) continue;
                s += wq[(dy + 1) * 3 + (dx + 1)] * xp[hh * HIMG + ww];
            }
        }
    }
    Y[((size_t)b * C2 + o) * HWN + p] = s;
}

// ---------------- attention helpers ----------------
__global__ void zero_S() {
    int i = blockIdx.x * 256 + threadIdx.x;
    if (i < 32 * CHD * CHD) g_S[i] = 0.f;
}

// row L2 norms of q (rows 0..47) and k (rows 48..95) per matrix m
__global__ void rownorm_kernel() {
    int m = blockIdx.x;       // 0..31
    int r = blockIdx.y;       // 0..95
    int b = m >> 3, br = (m >> 2) & 1, hh = m & 3;
    const float* base;
    if (r < CHD) {
        base = g_q + ((size_t)b * C2 + br * CC + hh * CHD + r) * HWN;
    } else {
        const float* src = br ? g_kv2 : g_kv1;
        base = src + ((size_t)b * C2 + hh * CHD + (r - CHD)) * HWN;
    }
    __shared__ float red[256];
    float s = 0.f;
    for (int i = threadIdx.x; i < HWN; i += 256) { float v = base[i]; s += v * v; }
    red[threadIdx.x] = s;
    __syncthreads();
    for (int st = 128; st > 0; st >>= 1) {
        if (threadIdx.x < st) red[threadIdx.x] += red[threadIdx.x + st];
        __syncthreads();
    }
    if (threadIdx.x == 0) g_nrm[m * 96 + r] = fmaxf(sqrtf(red[0]), 1e-12f);
}

// raw logits S[m][c][d] = q_c . k_d  (split-K over n, atomics)
__global__ void skernel() {
    int m = blockIdx.x, ns = blockIdx.y;   // 32 x 16
    int b = m >> 3, br = (m >> 2) & 1, hh = m & 3;
    const float* qb = g_q + ((size_t)b * C2 + br * CC + hh * CHD) * HWN;
    const float* kb = (br ? g_kv2 : g_kv1) + ((size_t)b * C2 + hh * CHD) * HWN;
    __shared__ float Qs[CHD][65];
    __shared__ float Ks[CHD][65];
    int t = threadIdx.x;
    int tx = t & 15, ty = t >> 4;
    float acc[3][3];
    #pragma unroll
    for (int i = 0; i < 3; i++)
        #pragma unroll
        for (int j = 0; j < 3; j++) acc[i][j] = 0.f;
    int nbeg = ns * 1024;
    for (int n0 = nbeg; n0 < nbeg + 1024; n0 += 64) {
        #pragma unroll
        for (int i = t; i < CHD * 64; i += 256) {
            int rr = i >> 6, cc = i & 63;
            Qs[rr][cc] = qb[(size_t)rr * HWN + n0 + cc];
            Ks[rr][cc] = kb[(size_t)rr * HWN + n0 + cc];
        }
        __syncthreads();
        #pragma unroll 8
        for (int kk = 0; kk < 64; kk++) {
            float qv[3], kv[3];
            #pragma unroll
            for (int i = 0; i < 3; i++) qv[i] = Qs[ty + 16 * i][kk];
            #pragma unroll
            for (int j = 0; j < 3; j++) kv[j] = Ks[tx + 16 * j][kk];
            #pragma unroll
            for (int i = 0; i < 3; i++)
                #pragma unroll
                for (int j = 0; j < 3; j++) acc[i][j] += qv[i] * kv[j];
        }
        __syncthreads();
    }
    #pragma unroll
    for (int i = 0; i < 3; i++)
        #pragma unroll
        for (int j = 0; j < 3; j++)
            atomicAdd(&g_S[m * CHD * CHD + (ty + 16 * i) * CHD + (tx + 16 * j)], acc[i][j]);
}

__global__ void softmax_kernel(const float* __restrict__ t1, const float* __restrict__ t2) {
    int m = blockIdx.x;
    int c = threadIdx.x;
    if (c >= CHD) return;
    int br = (m >> 2) & 1, hh = m & 3;
    float tmp = (br ? t2 : t1)[hh];
    float nq = g_nrm[m * 96 + c];
    float* row = g_S + (size_t)m * CHD * CHD + c * CHD;
    float vals[CHD];
    float mx = -1e30f;
    #pragma unroll
    for (int d = 0; d < CHD; d++) {
        float v = row[d] / (nq * g_nrm[m * 96 + CHD + d]) * tmp;
        vals[d] = v;
        mx = fmaxf(mx, v);
    }
    float sum = 0.f;
    #pragma unroll
    for (int d = 0; d < CHD; d++) { vals[d] = __expf(vals[d] - mx); sum += vals[d]; }
    float inv = 1.f / sum;
    #pragma unroll
    for (int d = 0; d < CHD; d++) row[d] = vals[d] * inv;
}

// out[c][p] = sum_d A[c][d] * v[d][p]
__global__ void av_kernel() {
    int m = blockIdx.x;
    int b = m >> 3, br = (m >> 2) & 1, hh = m & 3;
    __shared__ float As[CHD * CHD];
    for (int i = threadIdx.x; i < CHD * CHD; i += 128) As[i] = g_S[(size_t)m * CHD * CHD + i];
    __syncthreads();
    const float* vb = (br ? g_kv2 : g_kv1) + ((size_t)b * C2 + CC + hh * CHD) * HWN;
    float* ob = g_ao + ((size_t)b * C2 + br * CC + hh * CHD) * HWN;
    int p = blockIdx.y * 256 + threadIdx.x;
    float acc0[CHD], acc1[CHD];
    #pragma unroll
    for (int c = 0; c < CHD; c++) { acc0[c] = 0.f; acc1[c] = 0.f; }
    for (int d = 0; d < CHD; d++) {
        float v0 = vb[(size_t)d * HWN + p];
        float v1 = vb[(size_t)d * HWN + p + 128];
        #pragma unroll
        for (int c = 0; c < CHD; c++) {
            float a = As[c * CHD + d];
            acc0[c] += a * v0;
            acc1[c] += a * v1;
        }
    }
    #pragma unroll
    for (int c = 0; c < CHD; c++) {
        ob[(size_t)c * HWN + p] = acc0[c];
        ob[(size_t)c * HWN + p + 128] = acc1[c];
    }
}

// ---------------- gated gelu ----------------
__global__ void gelu_gate() {
    int b = blockIdx.z, c = blockIdx.y;
    int p = blockIdx.x * 256 + threadIdx.x;
    float a = g_hd[((size_t)b * HID2 + c) * HWN + p];
    float g = g_hd[((size_t)b * HID2 + HIDC + c) * HWN + p];
    float ge = 0.5f * a * (1.f + erff(a * 0.70710678118654752f));
    g_gg[((size_t)b * HIDC + c) * HWN + p] = ge * g;
}

// ---------------- launch ----------------
extern "C" void kernel_launch(void* const* d_in, const int* in_sizes, int n_in,
                              void* d_out, int out_size) {
    const float* x       = (const float*)d_in[0];
    const float* kv1in   = (const float*)d_in[1];
    const float* kv2in   = (const float*)d_in[2];
    const float* n1w = (const float*)d_in[3];  const float* n1b = (const float*)d_in[4];
    const float* nk1w = (const float*)d_in[5]; const float* nk1b = (const float*)d_in[6];
    const float* nk2w = (const float*)d_in[7]; const float* nk2b = (const float*)d_in[8];
    const float* n2w = (const float*)d_in[9];  const float* n2b = (const float*)d_in[10];
    const float* q_w   = (const float*)d_in[11];
    const float* kv1_w = (const float*)d_in[12];
    const float* kv2_w = (const float*)d_in[13];
    const float* q_dw  = (const float*)d_in[14];
    const float* kv1_dw= (const float*)d_in[15];
    const float* kv2_dw= (const float*)d_in[16];
    const float* proj_w= (const float*)d_in[17];
    const float* temp1 = (const float*)d_in[18];
    const float* temp2 = (const float*)d_in[19];
    const float* pin_w = (const float*)d_in[20];
    const float* dw_w  = (const float*)d_in[21];
    const float* pout_w= (const float*)d_in[22];
    float* out = (float*)d_out;

    float *p_xn, *p_kv1n, *p_kv2n, *p_qpre, *p_kv1pre, *p_kv2pre;
    float *p_q, *p_kv1, *p_kv2, *p_ao, *p_x2, *p_h, *p_hd, *p_gg;
    cudaGetSymbolAddress((void**)&p_xn, g_xn);
    cudaGetSymbolAddress((void**)&p_kv1n, g_kv1n);
    cudaGetSymbolAddress((void**)&p_kv2n, g_kv2n);
    cudaGetSymbolAddress((void**)&p_qpre, g_qpre);
    cudaGetSymbolAddress((void**)&p_kv1pre, g_kv1pre);
    cudaGetSymbolAddress((void**)&p_kv2pre, g_kv2pre);
    cudaGetSymbolAddress((void**)&p_q, g_q);
    cudaGetSymbolAddress((void**)&p_kv1, g_kv1);
    cudaGetSymbolAddress((void**)&p_kv2, g_kv2);
    cudaGetSymbolAddress((void**)&p_ao, g_ao);
    cudaGetSymbolAddress((void**)&p_x2, g_x2);
    cudaGetSymbolAddress((void**)&p_h, g_h);
    cudaGetSymbolAddress((void**)&p_hd, g_hd);
    cudaGetSymbolAddress((void**)&p_gg, g_gg);

    dim3 lnG(HWN / 256, BB);
    ln_kernel<<<lnG, 256>>>(x, n1w, n1b, p_xn);
    ln_kernel<<<lnG, 256>>>(kv1in, nk1w, nk1b, p_kv1n);
    ln_kernel<<<lnG, 256>>>(kv2in, nk2w, nk2b, p_kv2n);

    // 1x1 convs: 192 -> 384
    dim3 gQ(HWN / 128, 3, BB);
    gemm1x1<false><<<gQ, 256>>>(q_w,   p_xn,   nullptr, p_qpre,   C2, CC);
    gemm1x1<false><<<gQ, 256>>>(kv1_w, p_kv1n, nullptr, p_kv1pre, C2, CC);
    gemm1x1<false><<<gQ, 256>>>(kv2_w, p_kv2n, nullptr, p_kv2pre, C2, CC);

    // 3x3 grouped / depthwise
    dim3 dG(HWN / 256, C2, BB);
    dwconv_g2<<<dG, 256>>>(p_qpre, q_dw, p_q);
    dwconv_dw<<<dG, 256>>>(p_kv1pre, kv1_dw, p_kv1, C2);
    dwconv_dw<<<dG, 256>>>(p_kv2pre, kv2_dw, p_kv2, C2);

    // channel attention
    zero_S<<<(32 * CHD * CHD + 255) / 256, 256>>>();
    rownorm_kernel<<<dim3(32, 96), 256>>>();
    skernel<<<dim3(32, 16), 256>>>();
    softmax_kernel<<<32, 64>>>(temp1, temp2);
    av_kernel<<<dim3(32, HWN / 256), 128>>>();

    // proj (384 -> 192) + residual x
    dim3 gP(HWN / 128, 2, BB);
    gemm1x1<true><<<gP, 256>>>(proj_w, p_ao, x, p_x2, CC, C2);

    // FFN
    ln_kernel<<<lnG, 256>>>(p_x2, n2w, n2b, p_xn);
    dim3 gIn(HWN / 128, (HID2 + 127) / 128, BB);
    gemm1x1<false><<<gIn, 256>>>(pin_w, p_xn, nullptr, p_h, HID2, CC);
    dim3 dG2(HWN / 256, HID2, BB);
    dwconv_dw<<<dG2, 256>>>(p_h, dw_w, p_hd, HID2);
    dim3 gg(HWN / 256, HIDC, BB);
    gelu_gate<<<gg, 256>>>();
    gemm1x1<true><<<gP, 256>>>(pout_w, p_gg, p_x2, out, CC, HIDC);
}